// round 17
// baseline (speedup 1.0000x reference)
#include <cuda_runtime.h>
#include <cuda_bf16.h>
#include <cstdint>

// ShortConv: causal depthwise Conv1d (K=4) + SiLU.
// x: (B=4, L=4096, D=2048) fp32, D contiguous. w: (D, 1, 4) fp32.
// y[b,l,d] = silu( sum_{k=0..3} w[d,0,k] * x[b, l-3+k, d] ), OOB x -> 0.
//
// R16 vs R15-best (51.2us, ncu 42.0, DRAM 65% — 5x-reproduced plateau):
//  ONE change: y stores use DEFAULT cache policy instead of __stcs.
//  y (128MiB) nearly fits in L2 (126MB). Evict-first pushed writes to DRAM
//  eagerly, maximizing read/write turnarounds — the suspected plateau cause.
//  Default policy lets dirty lines linger in L2 and drain lazily, clearing
//  the DRAM bus for the read stream. Reads keep streaming hints (no reuse).
//  All structure identical to the proven optimum (depth-7 cp.async ring,
//  occ 5, regs 48, 740 balanced persistent CTAs).

#define DIM        2048
#define D4         (DIM / 4)       // 512 float4 per row
#define SEQLEN     4096
#define BATCH      4
#define THREADS    256
#define DGROUPS    (D4 / THREADS)  // 2
#define NCOLS      (BATCH * DGROUPS)          // 8
#define TOTAL_ROWS (NCOLS * SEQLEN)           // 32768
#define NCTAS      740                        // 148 SMs x occ 5
#define STAGES     8
#define STAGE_BYTES (THREADS * 16)            // 4KB per stage

__device__ __forceinline__ void cp_async16(uint32_t dst_smem, const void* src) {
    asm volatile("cp.async.cg.shared.global [%0], [%1], 16;\n"
                 :: "r"(dst_smem), "l"(src));
}
__device__ __forceinline__ void cp_commit() {
    asm volatile("cp.async.commit_group;\n");
}
__device__ __forceinline__ void cp_wait_allbutN() {  // wait until <= STAGES-2 pending
    asm volatile("cp.async.wait_group %0;\n" :: "n"(STAGES - 2));
}

__device__ __forceinline__ float silu1(float v) {
    // silu(v) = 0.5*v*(1 + tanh(v/2)); tanh.approx = 1 MUFU.
    float t, h = 0.5f * v;
    asm("tanh.approx.f32 %0, %1;" : "=f"(t) : "f"(h));
    return fmaf(h, t, h);
}

__global__ __launch_bounds__(THREADS, 5)
void shortconv_silu_kernel(const float4* __restrict__ x,
                           const float4* __restrict__ w4,
                           float4* __restrict__ y) {
    __shared__ float4 ring[STAGES][THREADS];

    const uint32_t ring_base =
        (uint32_t)__cvta_generic_to_shared(&ring[0][threadIdx.x]);

    const unsigned int cta = blockIdx.x;
    unsigned int r0 = (unsigned int)(((unsigned long long)cta       * TOTAL_ROWS) / NCTAS);
    const unsigned int r1 = (unsigned int)(((unsigned long long)(cta + 1) * TOTAL_ROWS) / NCTAS);

    const float4 zero = make_float4(0.f, 0.f, 0.f, 0.f);

    while (r0 < r1) {
        const unsigned int c = r0 >> 12;            // column: b*DGROUPS + dg
        const unsigned int l = r0 & (SEQLEN - 1);   // row within column
        const unsigned int seg_end = min(r1, (c + 1) << 12);
        const int n = (int)(seg_end - r0);

        const int dg = c & (DGROUPS - 1);
        const int b  = c >> 1;
        const int d4 = dg * THREADS + threadIdx.x;

        // Channel taps: w floats are [d*4+k]; this lane's 4 channels = 4 contiguous float4.
        const float4 wa = w4[d4 * 4 + 0];
        const float4 wb = w4[d4 * 4 + 1];
        const float4 wc = w4[d4 * 4 + 2];
        const float4 wd = w4[d4 * 4 + 3];

        const float4* xp = x + ((size_t)b * SEQLEN + l) * D4 + d4;
        float4*       yp = y + ((size_t)b * SEQLEN + l) * D4 + d4;

        // Causal window preload (overlaps with pipeline prologue).
        float4 xm3 = (l >= 3) ? __ldcs(xp - 3 * D4) : zero;
        float4 xm2 = (l >= 2) ? __ldcs(xp - 2 * D4) : zero;
        float4 xm1 = (l >= 1) ? __ldcs(xp - 1 * D4) : zero;

        // Pipeline prologue: issue rows 0..STAGES-2 (guarded), one group each.
        #pragma unroll
        for (int s = 0; s < STAGES - 1; ++s) {
            if (s < n) cp_async16(ring_base + s * STAGE_BYTES, xp + s * D4);
            cp_commit();
        }

        #pragma unroll 2
        for (int i = 0; i < n; ++i) {
            cp_wait_allbutN();                     // row i's group complete
            const float4 xc = ring[i & (STAGES - 1)][threadIdx.x];

            // Refill: row i+STAGES-1 into the stage freed last iteration.
            const int il = i + (STAGES - 1);
            if (il < n)
                cp_async16(ring_base + (il & (STAGES - 1)) * STAGE_BYTES, xp + il * D4);
            cp_commit();

            float4 r;
            r.x = fmaf(wa.x, xm3.x, fmaf(wa.y, xm2.x, fmaf(wa.z, xm1.x, wa.w * xc.x)));
            r.y = fmaf(wb.x, xm3.y, fmaf(wb.y, xm2.y, fmaf(wb.z, xm1.y, wb.w * xc.y)));
            r.z = fmaf(wc.x, xm3.z, fmaf(wc.y, xm2.z, fmaf(wc.z, xm1.z, wc.w * xc.z)));
            r.w = fmaf(wd.x, xm3.w, fmaf(wd.y, xm2.w, fmaf(wd.z, xm1.w, wd.w * xc.w)));

            r.x = silu1(r.x);
            r.y = silu1(r.y);
            r.z = silu1(r.z);
            r.w = silu1(r.w);

            // Default cache policy: let writes linger in L2 (y nearly fits).
            yp[i * D4] = r;

            xm3 = xm2; xm2 = xm1; xm1 = xc;
        }

        r0 = seg_end;
    }
}

extern "C" void kernel_launch(void* const* d_in, const int* in_sizes, int n_in,
                              void* d_out, int out_size) {
    const float4* x  = (const float4*)d_in[0];
    const float4* w4 = (const float4*)d_in[1];
    float4*       y  = (float4*)d_out;

    shortconv_silu_kernel<<<NCTAS, THREADS>>>(x, w4, y);
}